// round 12
// baseline (speedup 1.0000x reference)
#include <cuda_runtime.h>
#include <cuda_bf16.h>
#include <cstdint>

#define B_SZ   8
#define S_LEN  2048
#define E_DIM  768
#define H_DIM  128
#define M_TOTAL (B_SZ * S_LEN)

// hi/lo bf16 split inputs (produced by split kernels)
__device__ __nv_bfloat16 g_xh[M_TOTAL * E_DIM];
__device__ __nv_bfloat16 g_xl[M_TOTAL * E_DIM];
__device__ __nv_bfloat16 g_wh[3 * H_DIM * E_DIM];
__device__ __nv_bfloat16 g_wl[3 * H_DIM * E_DIM];
// hi/lo bf16 split q, k, v (q pre-scaled by 1/sqrt(128)), row-major
__device__ __nv_bfloat16 g_qh[M_TOTAL * H_DIM];
__device__ __nv_bfloat16 g_ql[M_TOTAL * H_DIM];
__device__ __nv_bfloat16 g_kh[M_TOTAL * H_DIM];
__device__ __nv_bfloat16 g_kl[M_TOTAL * H_DIM];
__device__ __nv_bfloat16 g_vh[M_TOTAL * H_DIM];
__device__ __nv_bfloat16 g_vl[M_TOTAL * H_DIM];
// split-KV partials (rows 1024..2047 of each batch)
__device__ float g_po[2 * 8 * 1024 * 128];
__device__ float g_pl[2 * 8 * 1024];

// ---------------------------------------------------------------------------
// helpers (baseline PTX only: mma.sync + ldmatrix + cp.async)
// ---------------------------------------------------------------------------
__device__ __forceinline__ uint32_t smem_u32(const void* p) {
    uint32_t a;
    asm("{ .reg .u64 t; cvta.to.shared.u64 t, %1; cvt.u32.u64 %0, t; }"
        : "=r"(a) : "l"(p));
    return a;
}
__device__ __forceinline__ void mma16816(float c[4],
                                         uint32_t a0, uint32_t a1, uint32_t a2, uint32_t a3,
                                         uint32_t b0, uint32_t b1) {
    asm volatile(
        "mma.sync.aligned.m16n8k16.row.col.f32.bf16.bf16.f32 "
        "{%0,%1,%2,%3}, {%4,%5,%6,%7}, {%8,%9}, {%0,%1,%2,%3};"
        : "+f"(c[0]), "+f"(c[1]), "+f"(c[2]), "+f"(c[3])
        : "r"(a0), "r"(a1), "r"(a2), "r"(a3), "r"(b0), "r"(b1));
}
__device__ __forceinline__ void ldmx4(uint32_t r[4], uint32_t addr) {
    asm volatile("ldmatrix.sync.aligned.m8n8.x4.shared.b16 {%0,%1,%2,%3}, [%4];"
                 : "=r"(r[0]), "=r"(r[1]), "=r"(r[2]), "=r"(r[3]) : "r"(addr));
}
__device__ __forceinline__ void ldmx4t(uint32_t r[4], uint32_t addr) {
    asm volatile("ldmatrix.sync.aligned.m8n8.x4.trans.shared.b16 {%0,%1,%2,%3}, [%4];"
                 : "=r"(r[0]), "=r"(r[1]), "=r"(r[2]), "=r"(r[3]) : "r"(addr));
}
__device__ __forceinline__ void cp16(uint32_t s, const void* g) {
    asm volatile("cp.async.cg.shared.global [%0], [%1], 16;" :: "r"(s), "l"(g));
}
#define CP_COMMIT()  asm volatile("cp.async.commit_group;" ::: "memory")
#define CP_WAIT1()   asm volatile("cp.async.wait_group 1;" ::: "memory")
#define CP_WAIT0()   asm volatile("cp.async.wait_group 0;" ::: "memory")

// hi/lo bf16 split of two floats packed bf16x2 (first value in low half)
__device__ __forceinline__ void split2(float a, float b, uint32_t& hi, uint32_t& lo) {
    __nv_bfloat16 ah = __float2bfloat16(a);
    __nv_bfloat16 bh = __float2bfloat16(b);
    __nv_bfloat16 al = __float2bfloat16(a - __bfloat162float(ah));
    __nv_bfloat16 bl = __float2bfloat16(b - __bfloat162float(bh));
    hi = ((uint32_t)__bfloat16_as_ushort(bh) << 16) | (uint32_t)__bfloat16_as_ushort(ah);
    lo = ((uint32_t)__bfloat16_as_ushort(bl) << 16) | (uint32_t)__bfloat16_as_ushort(al);
}

// ---------------------------------------------------------------------------
// Kernel 0a/0b: one-time hi/lo splits (memory-bound)
// ---------------------------------------------------------------------------
__global__ __launch_bounds__(256)
void split_x_kernel(const float* __restrict__ X, const float* __restrict__ mask)
{
    int idx = (blockIdx.x * 256 + threadIdx.x) * 4;
    float mk = mask[idx / E_DIM];
    float4 v = *(const float4*)&X[idx];
    uint32_t h0, l0, h1, l1;
    split2(v.x * mk, v.y * mk, h0, l0);
    split2(v.z * mk, v.w * mk, h1, l1);
    *(uint2*)&g_xh[idx] = make_uint2(h0, h1);
    *(uint2*)&g_xl[idx] = make_uint2(l0, l1);
}
__global__ __launch_bounds__(256)
void split_w_kernel(const float* __restrict__ Wq, const float* __restrict__ Wk,
                    const float* __restrict__ Wv)
{
    int idx = (blockIdx.x * 256 + threadIdx.x) * 4;
    int o = idx / (H_DIM * E_DIM);
    int r = idx - o * (H_DIM * E_DIM);
    const float* W = (o == 0) ? Wq : (o == 1 ? Wk : Wv);
    float4 v = *(const float4*)&W[r];
    uint32_t h0, l0, h1, l1;
    split2(v.x, v.y, h0, l0);
    split2(v.z, v.w, h1, l1);
    *(uint2*)&g_wh[idx] = make_uint2(h0, h1);
    *(uint2*)&g_wl[idx] = make_uint2(l0, l1);
}

// ---------------------------------------------------------------------------
// Kernel 1: QKV projection, bf16x3 warp MMA, cp.async double-buffered.
// grid=(256,3), block=128, 3 CTAs/SM.  BM=64, BN=128, BK=32 (24 chunks).
// Stage (bf16 elems, stride 40): Xh 0, Xl 2560, Wh 5120, Wl 10240; 15360
// elems = 30720 B per stage, x2 stages = 61440 B.
// ---------------------------------------------------------------------------
#define QAST 40
#define QSTG 15360
#define QKV_SMEM (2 * 30720)

__global__ __launch_bounds__(128, 3)
void qkv_mma_kernel()
{
    extern __shared__ __align__(16) __nv_bfloat16 sm_q[];
    const int tid  = threadIdx.x;
    const int lane = tid & 31;
    const int wid  = tid >> 5;
    const int m0   = blockIdx.x * 64;
    const int o    = blockIdx.y;
    const size_t wbase = (size_t)o * H_DIM * E_DIM;

    float c[16][4];
#pragma unroll
    for (int j = 0; j < 16; j++)
#pragma unroll
        for (int i = 0; i < 4; i++) c[j][i] = 0.f;

    auto issue = [&](int cc, int s) {
        uint32_t sb = smem_u32(sm_q + s * QSTG);
        const int k0 = cc * 32;
#pragma unroll
        for (int i = 0; i < 2; i++) {
            int idx = tid + i * 128;          // 0..255: X 64 rows x 4 chunks16
            int row = idx >> 2, c16 = idx & 3;
            size_t g = (size_t)(m0 + row) * E_DIM + k0 + c16 * 8;
            uint32_t d = sb + (row * QAST + c16 * 8) * 2;
            cp16(d,        &g_xh[g]);
            cp16(d + 5120, &g_xl[g]);
        }
#pragma unroll
        for (int i = 0; i < 4; i++) {
            int idx = tid + i * 128;          // 0..511: W 128 rows x 4 chunks16
            int row = idx >> 2, c16 = idx & 3;
            size_t g = wbase + (size_t)row * E_DIM + k0 + c16 * 8;
            uint32_t d = sb + (5120 + row * QAST + c16 * 8) * 2;
            cp16(d,         &g_wh[g]);
            cp16(d + 10240, &g_wl[g]);
        }
    };

    issue(0, 0); CP_COMMIT();

    const int brow = ((lane >> 4) & 1) * 8 + (lane & 7);
    const int bcol = ((lane >> 3) & 1) * 8;

    for (int cc = 0; cc < 24; cc++) {
        if (cc < 23) { issue(cc + 1, (cc + 1) & 1); CP_COMMIT(); CP_WAIT1(); }
        else CP_WAIT0();
        __syncthreads();

        const uint32_t xh_base = smem_u32(sm_q + (cc & 1) * QSTG);
        const uint32_t wh_base = xh_base + 10240;
#pragma unroll
        for (int kd = 0; kd < 2; kd++) {
            uint32_t ah[4], al[4];
            uint32_t aaddr = xh_base +
                ((wid * 16 + (lane & 15)) * QAST + kd * 16 + ((lane >> 4) << 3)) * 2;
            ldmx4(ah, aaddr);
            ldmx4(al, aaddr + 5120);
#pragma unroll
            for (int jp = 0; jp < 8; jp++) {
                uint32_t bh[4], bl[4];
                uint32_t baddr = wh_base +
                    ((jp * 16 + brow) * QAST + kd * 16 + bcol) * 2;
                ldmx4(bh, baddr);
                ldmx4(bl, baddr + 10240);
                mma16816(c[2 * jp],     ah[0], ah[1], ah[2], ah[3], bh[0], bh[1]);
                mma16816(c[2 * jp],     ah[0], ah[1], ah[2], ah[3], bl[0], bl[1]);
                mma16816(c[2 * jp],     al[0], al[1], al[2], al[3], bh[0], bh[1]);
                mma16816(c[2 * jp + 1], ah[0], ah[1], ah[2], ah[3], bh[2], bh[3]);
                mma16816(c[2 * jp + 1], ah[0], ah[1], ah[2], ah[3], bl[2], bl[3]);
                mma16816(c[2 * jp + 1], al[0], al[1], al[2], al[3], bh[2], bh[3]);
            }
        }
        __syncthreads();
    }

    const float sc = (o == 0) ? 0.0883883476483184f : 1.f;
    __nv_bfloat16* oh = (o == 0) ? g_qh : (o == 1 ? g_kh : g_vh);
    __nv_bfloat16* ol = (o == 0) ? g_ql : (o == 1 ? g_kl : g_vl);
    const size_t r0 = (size_t)(m0 + wid * 16 + (lane >> 2)) * H_DIM;
    const size_t r1 = r0 + 8 * H_DIM;
#pragma unroll
    for (int j = 0; j < 16; j++) {
        int col = j * 8 + (lane & 3) * 2;
        uint32_t h, l;
        split2(c[j][0] * sc, c[j][1] * sc, h, l);
        *(uint32_t*)&oh[r0 + col] = h;
        *(uint32_t*)&ol[r0 + col] = l;
        split2(c[j][2] * sc, c[j][3] * sc, h, l);
        *(uint32_t*)&oh[r1 + col] = h;
        *(uint32_t*)&ol[r1 + col] = l;
    }
}

// ---------------------------------------------------------------------------
// Kernel 2: causal flash attention.  QT=128, KT=64, block=512 (16 warps).
// Warp = (q-block qb 0..7) x (k-half kh 0..1): 16q x 32k S, partial O over
// its 32 keys; partials combined once at the end (no online rescale needed).
// grid=(24,8): bx<16 -> split-KV halves for qt=15-(bx>>1); bx>=16 -> qt=23-bx.
// smem (bf16 elems): Qh 0, Ql 17408; KV stage s @ 34816+s*34816:
//   Kh +0, Kl +8704, Vh +17408, Vl +26112.  Total 208896 B.
// ---------------------------------------------------------------------------
#define AST 136
#define KVSTG_E 34816
#define ATT_SMEM 208896

__global__ __launch_bounds__(512)
void attn_mma_kernel(float* __restrict__ out)
{
    extern __shared__ __align__(16) __nv_bfloat16 sm_a[];

    const int tid  = threadIdx.x;
    const int lane = tid & 31;
    const int wid  = tid >> 5;
    const int qb   = wid & 7;
    const int kh   = wid >> 3;
    const int b    = blockIdx.y;
    const int bx   = blockIdx.x;

    int qt, h, sbeg, send;
    bool split_kv;
    if (bx < 16) {
        split_kv = true;
        qt   = 15 - (bx >> 1);
        h    = bx & 1;
        sbeg = h * (qt + 1);
        send = sbeg + qt + 1;
    } else {
        split_kv = false;
        qt   = 23 - bx;
        h    = 0;
        sbeg = 0;
        send = 2 * qt + 2;
    }
    const int q0 = qt * 128;

    const uint32_t qh_base = smem_u32(sm_a);

    auto issue_kv = [&](int kts, int s) {
        uint32_t kb = smem_u32(sm_a + 34816 + s * KVSTG_E);
#pragma unroll
        for (int i = 0; i < 2; i++) {
            int idx = tid + i * 512;           // 0..1023: 64 rows x 16 chunks
            int row = idx >> 4, c8 = idx & 15;
            size_t g = ((size_t)b * S_LEN + kts * 64 + row) * H_DIM + c8 * 8;
            uint32_t d = kb + (row * AST + c8 * 8) * 2;
            cp16(d,         &g_kh[g]);
            cp16(d + 17408, &g_kl[g]);
            cp16(d + 34816, &g_vh[g]);
            cp16(d + 52224, &g_vl[g]);
        }
    };

    issue_kv(sbeg, sbeg & 1); CP_COMMIT();

    // --- stage Q (hi/lo), 128 rows ---
#pragma unroll
    for (int i = 0; i < 4; i++) {
        int idx = tid + i * 512;               // 0..2047
        int row = idx >> 4, c8 = idx & 15;
        size_t g = ((size_t)b * S_LEN + q0 + row) * H_DIM + c8 * 8;
        *(uint4*)&sm_a[row * AST + c8 * 8]         = *(const uint4*)&g_qh[g];
        *(uint4*)&sm_a[17408 + row * AST + c8 * 8] = *(const uint4*)&g_ql[g];
    }

    float o_[16][4];
#pragma unroll
    for (int d = 0; d < 16; d++)
#pragma unroll
        for (int i = 0; i < 4; i++) o_[d][i] = 0.f;
    float lsum0 = 0.f, lsum1 = 0.f;

    const int colb = (lane & 3) * 2;
    const int r0l  = qb * 16 + (lane >> 2);
    const int r1l  = r0l + 8;
    const int kbrow = ((lane >> 4) & 1) * 8 + (lane & 7);
    const int kbcol = ((lane >> 3) & 1) * 8;
    const int vbrow = ((lane >> 3) & 1) * 8 + (lane & 7);
    const int vbcol = ((lane >> 4) & 1) * 8;

    for (int kts = sbeg; kts < send; kts++) {
        if (kts + 1 < send) { issue_kv(kts + 1, (kts + 1) & 1); CP_COMMIT(); CP_WAIT1(); }
        else CP_WAIT0();
        __syncthreads();

        const uint32_t kb = smem_u32(sm_a + 34816 + (kts & 1) * KVSTG_E);
        const uint32_t vb = kb + 34816;        // Vh bytes

        // --- S = Q K^T  (this warp: 16 q x 32 k, keys kh*32..+31 of tile) ---
        float s[4][4];
#pragma unroll
        for (int j = 0; j < 4; j++)
#pragma unroll
            for (int i = 0; i < 4; i++) s[j][i] = 0.f;

#pragma unroll
        for (int kd = 0; kd < 8; kd++) {
            uint32_t ah[4], al[4];
            uint32_t aaddr = qh_base +
                ((qb * 16 + (lane & 15)) * AST + kd * 16 + ((lane >> 4) << 3)) * 2;
            ldmx4(ah, aaddr);
            ldmx4(al, aaddr + 34816);
#pragma unroll
            for (int jp = 0; jp < 2; jp++) {
                uint32_t bh[4], bl[4];
                uint32_t baddr = kb +
                    ((kh * 32 + jp * 16 + kbrow) * AST + kd * 16 + kbcol) * 2;
                ldmx4(bh, baddr);
                ldmx4(bl, baddr + 17408);
                mma16816(s[2 * jp],     ah[0], ah[1], ah[2], ah[3], bh[0], bh[1]);
                mma16816(s[2 * jp],     ah[0], ah[1], ah[2], ah[3], bl[0], bl[1]);
                mma16816(s[2 * jp],     al[0], al[1], al[2], al[3], bh[0], bh[1]);
                mma16816(s[2 * jp + 1], ah[0], ah[1], ah[2], ah[3], bh[2], bh[3]);
                mma16816(s[2 * jp + 1], ah[0], ah[1], ah[2], ah[3], bl[2], bl[3]);
                mma16816(s[2 * jp + 1], al[0], al[1], al[2], al[3], bh[2], bh[3]);
            }
        }

        // --- exp (+ causal mask), partial row sums ---
        const bool diag = (kts >= 2 * qt);
        const int dof = kts * 64 - q0 + kh * 32;
        float rs0 = 0.f, rs1 = 0.f;
#pragma unroll
        for (int j = 0; j < 4; j++) {
            float e0 = __expf(s[j][0]);
            float e1 = __expf(s[j][1]);
            float e2 = __expf(s[j][2]);
            float e3 = __expf(s[j][3]);
            if (diag) {
                int cc = j * 8 + colb + dof;
                if (cc     > r0l) e0 = 0.f;
                if (cc + 1 > r0l) e1 = 0.f;
                if (cc     > r1l) e2 = 0.f;
                if (cc + 1 > r1l) e3 = 0.f;
            }
            s[j][0] = e0; s[j][1] = e1; s[j][2] = e2; s[j][3] = e3;
            rs0 += e0 + e1;
            rs1 += e2 + e3;
        }
        rs0 += __shfl_xor_sync(0xffffffffu, rs0, 1);
        rs0 += __shfl_xor_sync(0xffffffffu, rs0, 2);
        rs1 += __shfl_xor_sync(0xffffffffu, rs1, 1);
        rs1 += __shfl_xor_sync(0xffffffffu, rs1, 2);
        lsum0 += rs0;
        lsum1 += rs1;

        // --- O += P V over this warp's 32 keys ---
#pragma unroll
        for (int j2 = 0; j2 < 2; j2++) {
            uint32_t ph[4], pl[4];
            split2(s[2 * j2][0],     s[2 * j2][1],     ph[0], pl[0]);
            split2(s[2 * j2][2],     s[2 * j2][3],     ph[1], pl[1]);
            split2(s[2 * j2 + 1][0], s[2 * j2 + 1][1], ph[2], pl[2]);
            split2(s[2 * j2 + 1][2], s[2 * j2 + 1][3], ph[3], pl[3]);
#pragma unroll
            for (int d2 = 0; d2 < 8; d2++) {
                uint32_t vh[4], vl[4];
                uint32_t vaddr = vb +
                    ((kh * 32 + j2 * 16 + vbrow) * AST + d2 * 16 + vbcol) * 2;
                ldmx4t(vh, vaddr);
                ldmx4t(vl, vaddr + 17408);
                mma16816(o_[2 * d2],     ph[0], ph[1], ph[2], ph[3], vh[0], vh[1]);
                mma16816(o_[2 * d2],     ph[0], ph[1], ph[2], ph[3], vl[0], vl[1]);
                mma16816(o_[2 * d2],     pl[0], pl[1], pl[2], pl[3], vh[0], vh[1]);
                mma16816(o_[2 * d2 + 1], ph[0], ph[1], ph[2], ph[3], vh[2], vh[3]);
                mma16816(o_[2 * d2 + 1], ph[0], ph[1], ph[2], ph[3], vl[2], vl[3]);
                mma16816(o_[2 * d2 + 1], pl[0], pl[1], pl[2], pl[3], vh[2], vh[3]);
            }
        }
        __syncthreads();
    }

    // --- combine k-half partials via smem scratch (reuse KV area) ---
    float* scr = (float*)(sm_a + 34816);       // [128][132] + lsum[128]
    float* ls  = scr + 128 * 132;
    if (kh == 1) {
#pragma unroll
        for (int dn = 0; dn < 16; dn++) {
            int col = dn * 8 + colb;
            scr[r0l * 132 + col]     = o_[dn][0];
            scr[r0l * 132 + col + 1] = o_[dn][1];
            scr[r1l * 132 + col]     = o_[dn][2];
            scr[r1l * 132 + col + 1] = o_[dn][3];
        }
        if ((lane & 3) == 0) { ls[r0l] = lsum0; ls[r1l] = lsum1; }
    }
    __syncthreads();
    if (kh == 0) {
#pragma unroll
        for (int dn = 0; dn < 16; dn++) {
            int col = dn * 8 + colb;
            o_[dn][0] += scr[r0l * 132 + col];
            o_[dn][1] += scr[r0l * 132 + col + 1];
            o_[dn][2] += scr[r1l * 132 + col];
            o_[dn][3] += scr[r1l * 132 + col + 1];
        }
        lsum0 += ls[r0l];
        lsum1 += ls[r1l];

        if (!split_kv) {
            const float inv0 = 1.f / lsum0;
            const float inv1 = 1.f / lsum1;
            const size_t gr0 = ((size_t)b * S_LEN + q0 + r0l) * H_DIM;
            const size_t gr1 = gr0 + 8 * H_DIM;
#pragma unroll
            for (int dn = 0; dn < 16; dn++) {
                int col = dn * 8 + colb;
                *(float2*)&out[gr0 + col] = make_float2(o_[dn][0] * inv0, o_[dn][1] * inv0);
                *(float2*)&out[gr1 + col] = make_float2(o_[dn][2] * inv1, o_[dn][3] * inv1);
            }
        } else {
            const size_t pbase = (size_t)(h * 8 + b) * 1024 + (q0 - 1024);
            float* p0 = &g_po[(pbase + r0l) * 128];
            float* p1 = &g_po[(pbase + r1l) * 128];
#pragma unroll
            for (int dn = 0; dn < 16; dn++) {
                int col = dn * 8 + colb;
                *(float2*)&p0[col] = make_float2(o_[dn][0], o_[dn][1]);
                *(float2*)&p1[col] = make_float2(o_[dn][2], o_[dn][3]);
            }
            if ((lane & 3) == 0) {
                g_pl[pbase + r0l] = lsum0;
                g_pl[pbase + r1l] = lsum1;
            }
        }
    }
}

// ---------------------------------------------------------------------------
// Kernel 3: combine split-KV partials (rows 1024..2047 of each batch)
// ---------------------------------------------------------------------------
__global__ __launch_bounds__(256)
void combine_kernel(float* __restrict__ out)
{
    int idx = blockIdx.x * 256 + threadIdx.x;
    int row = idx >> 5;
    int d4  = (idx & 31) * 4;
    int b   = row >> 10;
    int r   = row & 1023;
    float l = g_pl[(size_t)b * 1024 + r] + g_pl[(size_t)(8 + b) * 1024 + r];
    float inv = 1.f / l;
    size_t i0 = ((size_t)b * 1024 + r) * 128 + d4;
    size_t i1 = ((size_t)(8 + b) * 1024 + r) * 128 + d4;
    float4 a = *(const float4*)&g_po[i0];
    float4 c = *(const float4*)&g_po[i1];
    float4 o;
    o.x = (a.x + c.x) * inv;
    o.y = (a.y + c.y) * inv;
    o.z = (a.z + c.z) * inv;
    o.w = (a.w + c.w) * inv;
    *(float4*)&out[((size_t)b * S_LEN + 1024 + r) * H_DIM + d4] = o;
}

// ---------------------------------------------------------------------------
extern "C" void kernel_launch(void* const* d_in, const int* in_sizes, int n_in,
                              void* d_out, int out_size)
{
    const float* X    = (const float*)d_in[0];
    const float* mask = (const float*)d_in[1];
    const float* Wq   = (const float*)d_in[2];
    const float* Wk   = (const float*)d_in[3];
    const float* Wv   = (const float*)d_in[4];
    float* out        = (float*)d_out;

    split_x_kernel<<<M_TOTAL * E_DIM / 4 / 256, 256>>>(X, mask);
    split_w_kernel<<<3 * H_DIM * E_DIM / 4 / 256, 256>>>(Wq, Wk, Wv);

    cudaFuncSetAttribute(qkv_mma_kernel,
                         cudaFuncAttributeMaxDynamicSharedMemorySize, QKV_SMEM);
    dim3 g1(M_TOTAL / 64, 3);
    qkv_mma_kernel<<<g1, 128, QKV_SMEM>>>();

    cudaFuncSetAttribute(attn_mma_kernel,
                         cudaFuncAttributeMaxDynamicSharedMemorySize, ATT_SMEM);
    dim3 g2(24, B_SZ);
    attn_mma_kernel<<<g2, 512, ATT_SMEM>>>(out);

    combine_kernel<<<1024, 256>>>(out);
}

// round 13
// speedup vs baseline: 1.0134x; 1.0134x over previous
#include <cuda_runtime.h>
#include <cuda_bf16.h>
#include <cstdint>

#define B_SZ   8
#define S_LEN  2048
#define E_DIM  768
#define H_DIM  128
#define M_TOTAL (B_SZ * S_LEN)

// hi/lo bf16 split inputs (produced by split kernels)
__device__ __nv_bfloat16 g_xh[M_TOTAL * E_DIM];
__device__ __nv_bfloat16 g_xl[M_TOTAL * E_DIM];
__device__ __nv_bfloat16 g_wh[3 * H_DIM * E_DIM];
__device__ __nv_bfloat16 g_wl[3 * H_DIM * E_DIM];
// hi/lo bf16 split q, k, v (q pre-scaled by 1/sqrt(128)), row-major
__device__ __nv_bfloat16 g_qh[M_TOTAL * H_DIM];
__device__ __nv_bfloat16 g_ql[M_TOTAL * H_DIM];
__device__ __nv_bfloat16 g_kh[M_TOTAL * H_DIM];
__device__ __nv_bfloat16 g_kl[M_TOTAL * H_DIM];
__device__ __nv_bfloat16 g_vh[M_TOTAL * H_DIM];
__device__ __nv_bfloat16 g_vl[M_TOTAL * H_DIM];
// split-KV partials (rows 1024..2047 of each batch)
__device__ float g_po[2 * 8 * 1024 * 128];
__device__ float g_pl[2 * 8 * 1024];

// ---------------------------------------------------------------------------
// helpers (baseline PTX only: mma.sync + ldmatrix + cp.async)
// ---------------------------------------------------------------------------
__device__ __forceinline__ uint32_t smem_u32(const void* p) {
    uint32_t a;
    asm("{ .reg .u64 t; cvta.to.shared.u64 t, %1; cvt.u32.u64 %0, t; }"
        : "=r"(a) : "l"(p));
    return a;
}
__device__ __forceinline__ void mma16816(float c[4],
                                         uint32_t a0, uint32_t a1, uint32_t a2, uint32_t a3,
                                         uint32_t b0, uint32_t b1) {
    asm volatile(
        "mma.sync.aligned.m16n8k16.row.col.f32.bf16.bf16.f32 "
        "{%0,%1,%2,%3}, {%4,%5,%6,%7}, {%8,%9}, {%0,%1,%2,%3};"
        : "+f"(c[0]), "+f"(c[1]), "+f"(c[2]), "+f"(c[3])
        : "r"(a0), "r"(a1), "r"(a2), "r"(a3), "r"(b0), "r"(b1));
}
__device__ __forceinline__ void ldmx4(uint32_t r[4], uint32_t addr) {
    asm volatile("ldmatrix.sync.aligned.m8n8.x4.shared.b16 {%0,%1,%2,%3}, [%4];"
                 : "=r"(r[0]), "=r"(r[1]), "=r"(r[2]), "=r"(r[3]) : "r"(addr));
}
__device__ __forceinline__ void ldmx4t(uint32_t r[4], uint32_t addr) {
    asm volatile("ldmatrix.sync.aligned.m8n8.x4.trans.shared.b16 {%0,%1,%2,%3}, [%4];"
                 : "=r"(r[0]), "=r"(r[1]), "=r"(r[2]), "=r"(r[3]) : "r"(addr));
}
__device__ __forceinline__ void cp16(uint32_t s, const void* g) {
    asm volatile("cp.async.cg.shared.global [%0], [%1], 16;" :: "r"(s), "l"(g));
}
#define CP_COMMIT()  asm volatile("cp.async.commit_group;" ::: "memory")
#define CP_WAIT1()   asm volatile("cp.async.wait_group 1;" ::: "memory")
#define CP_WAIT0()   asm volatile("cp.async.wait_group 0;" ::: "memory")

// hi/lo bf16 split of two floats packed bf16x2 (first value in low half)
__device__ __forceinline__ void split2(float a, float b, uint32_t& hi, uint32_t& lo) {
    __nv_bfloat16 ah = __float2bfloat16(a);
    __nv_bfloat16 bh = __float2bfloat16(b);
    __nv_bfloat16 al = __float2bfloat16(a - __bfloat162float(ah));
    __nv_bfloat16 bl = __float2bfloat16(b - __bfloat162float(bh));
    hi = ((uint32_t)__bfloat16_as_ushort(bh) << 16) | (uint32_t)__bfloat16_as_ushort(ah);
    lo = ((uint32_t)__bfloat16_as_ushort(bl) << 16) | (uint32_t)__bfloat16_as_ushort(al);
}

// ---------------------------------------------------------------------------
// Kernel 0a/0b: one-time hi/lo splits (memory-bound)
// ---------------------------------------------------------------------------
__global__ __launch_bounds__(256)
void split_x_kernel(const float* __restrict__ X, const float* __restrict__ mask)
{
    int idx = (blockIdx.x * 256 + threadIdx.x) * 4;
    float mk = mask[idx / E_DIM];
    float4 v = *(const float4*)&X[idx];
    uint32_t h0, l0, h1, l1;
    split2(v.x * mk, v.y * mk, h0, l0);
    split2(v.z * mk, v.w * mk, h1, l1);
    *(uint2*)&g_xh[idx] = make_uint2(h0, h1);
    *(uint2*)&g_xl[idx] = make_uint2(l0, l1);
}
__global__ __launch_bounds__(256)
void split_w_kernel(const float* __restrict__ Wq, const float* __restrict__ Wk,
                    const float* __restrict__ Wv)
{
    int idx = (blockIdx.x * 256 + threadIdx.x) * 4;
    int o = idx / (H_DIM * E_DIM);
    int r = idx - o * (H_DIM * E_DIM);
    const float* W = (o == 0) ? Wq : (o == 1 ? Wk : Wv);
    float4 v = *(const float4*)&W[r];
    uint32_t h0, l0, h1, l1;
    split2(v.x, v.y, h0, l0);
    split2(v.z, v.w, h1, l1);
    *(uint2*)&g_wh[idx] = make_uint2(h0, h1);
    *(uint2*)&g_wl[idx] = make_uint2(l0, l1);
}

// ---------------------------------------------------------------------------
// Kernel 1: QKV projection, bf16x3 warp MMA, cp.async double-buffered.
// grid=(128,3), block=128 (4 warps, each 32 m-rows x 128 n).  BM=128, BK=32.
// Stage (bf16 elems, stride 40): Xh 0, Xl 5120, Wh 10240, Wl 15360; 20480
// elems = 40960 B per stage x2 = 81920 B -> 2 CTAs/SM.
// ---------------------------------------------------------------------------
#define QAST 40
#define QSTG 20480
#define QKV_SMEM (2 * 40960)

__global__ __launch_bounds__(128, 2)
void qkv_mma_kernel()
{
    extern __shared__ __align__(16) __nv_bfloat16 sm_q[];
    const int tid  = threadIdx.x;
    const int lane = tid & 31;
    const int wid  = tid >> 5;
    const int m0   = blockIdx.x * 128;
    const int o    = blockIdx.y;
    const size_t wbase = (size_t)o * H_DIM * E_DIM;

    float c[2][16][4];
#pragma unroll
    for (int mb = 0; mb < 2; mb++)
#pragma unroll
        for (int j = 0; j < 16; j++)
#pragma unroll
            for (int i = 0; i < 4; i++) c[mb][j][i] = 0.f;

    auto issue = [&](int cc, int s) {
        uint32_t sb = smem_u32(sm_q + s * QSTG);
        const int k0 = cc * 32;
#pragma unroll
        for (int i = 0; i < 4; i++) {
            int idx = tid + i * 128;          // 0..511: X 128 rows x 4 chunks16
            int row = idx >> 2, c16 = idx & 3;
            size_t g = (size_t)(m0 + row) * E_DIM + k0 + c16 * 8;
            uint32_t d = sb + (row * QAST + c16 * 8) * 2;
            cp16(d,         &g_xh[g]);
            cp16(d + 10240, &g_xl[g]);
        }
#pragma unroll
        for (int i = 0; i < 4; i++) {
            int idx = tid + i * 128;          // 0..511: W 128 rows x 4 chunks16
            int row = idx >> 2, c16 = idx & 3;
            size_t g = wbase + (size_t)row * E_DIM + k0 + c16 * 8;
            uint32_t d = sb + (10240 + row * QAST + c16 * 8) * 2;
            cp16(d,         &g_wh[g]);
            cp16(d + 10240, &g_wl[g]);
        }
    };

    issue(0, 0); CP_COMMIT();

    const int brow = ((lane >> 4) & 1) * 8 + (lane & 7);
    const int bcol = ((lane >> 3) & 1) * 8;

    for (int cc = 0; cc < 24; cc++) {
        if (cc < 23) { issue(cc + 1, (cc + 1) & 1); CP_COMMIT(); CP_WAIT1(); }
        else CP_WAIT0();
        __syncthreads();

        const uint32_t xh_base = smem_u32(sm_q + (cc & 1) * QSTG);
        const uint32_t wh_base = xh_base + 20480;
#pragma unroll
        for (int kd = 0; kd < 2; kd++) {
            uint32_t ah[2][4], al[2][4];
#pragma unroll
            for (int mb = 0; mb < 2; mb++) {
                uint32_t aaddr = xh_base +
                    ((wid * 32 + mb * 16 + (lane & 15)) * QAST + kd * 16 +
                     ((lane >> 4) << 3)) * 2;
                ldmx4(ah[mb], aaddr);
                ldmx4(al[mb], aaddr + 10240);
            }
#pragma unroll
            for (int jp = 0; jp < 8; jp++) {
                uint32_t bh[4], bl[4];
                uint32_t baddr = wh_base +
                    ((jp * 16 + brow) * QAST + kd * 16 + bcol) * 2;
                ldmx4(bh, baddr);
                ldmx4(bl, baddr + 10240);
#pragma unroll
                for (int mb = 0; mb < 2; mb++) {
                    mma16816(c[mb][2 * jp],     ah[mb][0], ah[mb][1], ah[mb][2], ah[mb][3], bh[0], bh[1]);
                    mma16816(c[mb][2 * jp],     ah[mb][0], ah[mb][1], ah[mb][2], ah[mb][3], bl[0], bl[1]);
                    mma16816(c[mb][2 * jp],     al[mb][0], al[mb][1], al[mb][2], al[mb][3], bh[0], bh[1]);
                    mma16816(c[mb][2 * jp + 1], ah[mb][0], ah[mb][1], ah[mb][2], ah[mb][3], bh[2], bh[3]);
                    mma16816(c[mb][2 * jp + 1], ah[mb][0], ah[mb][1], ah[mb][2], ah[mb][3], bl[2], bl[3]);
                    mma16816(c[mb][2 * jp + 1], al[mb][0], al[mb][1], al[mb][2], al[mb][3], bh[2], bh[3]);
                }
            }
        }
        __syncthreads();
    }

    const float sc = (o == 0) ? 0.0883883476483184f : 1.f;
    __nv_bfloat16* oh = (o == 0) ? g_qh : (o == 1 ? g_kh : g_vh);
    __nv_bfloat16* ol = (o == 0) ? g_ql : (o == 1 ? g_kl : g_vl);
#pragma unroll
    for (int mb = 0; mb < 2; mb++) {
        const size_t r0 = (size_t)(m0 + wid * 32 + mb * 16 + (lane >> 2)) * H_DIM;
        const size_t r1 = r0 + 8 * H_DIM;
#pragma unroll
        for (int j = 0; j < 16; j++) {
            int col = j * 8 + (lane & 3) * 2;
            uint32_t h, l;
            split2(c[mb][j][0] * sc, c[mb][j][1] * sc, h, l);
            *(uint32_t*)&oh[r0 + col] = h;
            *(uint32_t*)&ol[r0 + col] = l;
            split2(c[mb][j][2] * sc, c[mb][j][3] * sc, h, l);
            *(uint32_t*)&oh[r1 + col] = h;
            *(uint32_t*)&ol[r1 + col] = l;
        }
    }
}

// ---------------------------------------------------------------------------
// Kernel 2: causal flash attention.  QT=128, KT=64, block=256 (8 warps).
// Warp = (q-group qg 0..3, 32 rows) x (k-half kh 0..1, 32 keys): 32q x 32k S,
// partial O over its 32 keys; kh partials combined exactly at the end.
// grid=(24,8): bx<16 -> split-KV halves for qt=15-(bx>>1); bx>=16 -> qt=23-bx.
// smem (bf16 elems): Qh 0, Ql 17408; KV stage s @ 34816+s*34816:
//   Kh +0, Kl +8704, Vh +17408, Vl +26112.  Total 208896 B.
// ---------------------------------------------------------------------------
#define AST 136
#define KVSTG_E 34816
#define ATT_SMEM 208896

__global__ __launch_bounds__(256, 1)
void attn_mma_kernel(float* __restrict__ out)
{
    extern __shared__ __align__(16) __nv_bfloat16 sm_a[];

    const int tid  = threadIdx.x;
    const int lane = tid & 31;
    const int wid  = tid >> 5;
    const int qg   = wid & 3;
    const int kh   = wid >> 2;
    const int b    = blockIdx.y;
    const int bx   = blockIdx.x;

    int qt, h, sbeg, send;
    bool split_kv;
    if (bx < 16) {
        split_kv = true;
        qt   = 15 - (bx >> 1);
        h    = bx & 1;
        sbeg = h * (qt + 1);
        send = sbeg + qt + 1;
    } else {
        split_kv = false;
        qt   = 23 - bx;
        h    = 0;
        sbeg = 0;
        send = 2 * qt + 2;
    }
    const int q0 = qt * 128;

    const uint32_t qh_base = smem_u32(sm_a);

    auto issue_kv = [&](int kts, int s) {
        uint32_t kb = smem_u32(sm_a + 34816 + s * KVSTG_E);
#pragma unroll
        for (int i = 0; i < 4; i++) {
            int idx = tid + i * 256;           // 0..1023: 64 rows x 16 chunks
            int row = idx >> 4, c8 = idx & 15;
            size_t g = ((size_t)b * S_LEN + kts * 64 + row) * H_DIM + c8 * 8;
            uint32_t d = kb + (row * AST + c8 * 8) * 2;
            cp16(d,         &g_kh[g]);
            cp16(d + 17408, &g_kl[g]);
            cp16(d + 34816, &g_vh[g]);
            cp16(d + 52224, &g_vl[g]);
        }
    };

    issue_kv(sbeg, sbeg & 1); CP_COMMIT();

    // --- stage Q (hi/lo), 128 rows ---
#pragma unroll
    for (int i = 0; i < 8; i++) {
        int idx = tid + i * 256;               // 0..2047
        int row = idx >> 4, c8 = idx & 15;
        size_t g = ((size_t)b * S_LEN + q0 + row) * H_DIM + c8 * 8;
        *(uint4*)&sm_a[row * AST + c8 * 8]         = *(const uint4*)&g_qh[g];
        *(uint4*)&sm_a[17408 + row * AST + c8 * 8] = *(const uint4*)&g_ql[g];
    }

    float o_[2][16][4];
#pragma unroll
    for (int mb = 0; mb < 2; mb++)
#pragma unroll
        for (int d = 0; d < 16; d++)
#pragma unroll
            for (int i = 0; i < 4; i++) o_[mb][d][i] = 0.f;
    float lsum[2][2] = {{0.f, 0.f}, {0.f, 0.f}};

    const int colb = (lane & 3) * 2;
    const int kbrow = ((lane >> 4) & 1) * 8 + (lane & 7);
    const int kbcol = ((lane >> 3) & 1) * 8;
    const int vbrow = ((lane >> 3) & 1) * 8 + (lane & 7);
    const int vbcol = ((lane >> 4) & 1) * 8;

    for (int kts = sbeg; kts < send; kts++) {
        if (kts + 1 < send) { issue_kv(kts + 1, (kts + 1) & 1); CP_COMMIT(); CP_WAIT1(); }
        else CP_WAIT0();
        __syncthreads();

        const uint32_t kb = smem_u32(sm_a + 34816 + (kts & 1) * KVSTG_E);
        const uint32_t vb = kb + 34816;        // Vh bytes

        // --- S = Q K^T  (this warp: 32 q x 32 k) ---
        float s[2][4][4];
#pragma unroll
        for (int mb = 0; mb < 2; mb++)
#pragma unroll
            for (int j = 0; j < 4; j++)
#pragma unroll
                for (int i = 0; i < 4; i++) s[mb][j][i] = 0.f;

#pragma unroll
        for (int kd = 0; kd < 8; kd++) {
            uint32_t ah[2][4], al[2][4];
#pragma unroll
            for (int mb = 0; mb < 2; mb++) {
                uint32_t aaddr = qh_base +
                    ((qg * 32 + mb * 16 + (lane & 15)) * AST + kd * 16 +
                     ((lane >> 4) << 3)) * 2;
                ldmx4(ah[mb], aaddr);
                ldmx4(al[mb], aaddr + 34816);
            }
#pragma unroll
            for (int jp = 0; jp < 2; jp++) {
                uint32_t bh[4], bl[4];
                uint32_t baddr = kb +
                    ((kh * 32 + jp * 16 + kbrow) * AST + kd * 16 + kbcol) * 2;
                ldmx4(bh, baddr);
                ldmx4(bl, baddr + 17408);
#pragma unroll
                for (int mb = 0; mb < 2; mb++) {
                    mma16816(s[mb][2 * jp],     ah[mb][0], ah[mb][1], ah[mb][2], ah[mb][3], bh[0], bh[1]);
                    mma16816(s[mb][2 * jp],     ah[mb][0], ah[mb][1], ah[mb][2], ah[mb][3], bl[0], bl[1]);
                    mma16816(s[mb][2 * jp],     al[mb][0], al[mb][1], al[mb][2], al[mb][3], bh[0], bh[1]);
                    mma16816(s[mb][2 * jp + 1], ah[mb][0], ah[mb][1], ah[mb][2], ah[mb][3], bh[2], bh[3]);
                    mma16816(s[mb][2 * jp + 1], ah[mb][0], ah[mb][1], ah[mb][2], ah[mb][3], bl[2], bl[3]);
                    mma16816(s[mb][2 * jp + 1], al[mb][0], al[mb][1], al[mb][2], al[mb][3], bh[2], bh[3]);
                }
            }
        }

        // --- exp (+ causal mask), partial row sums ---
        const bool diag = (kts >= 2 * qt);
        const int dof = kts * 64 - q0 + kh * 32;
#pragma unroll
        for (int mb = 0; mb < 2; mb++) {
            const int r0l = qg * 32 + mb * 16 + (lane >> 2);
            const int r1l = r0l + 8;
            float rs0 = 0.f, rs1 = 0.f;
#pragma unroll
            for (int j = 0; j < 4; j++) {
                float e0 = __expf(s[mb][j][0]);
                float e1 = __expf(s[mb][j][1]);
                float e2 = __expf(s[mb][j][2]);
                float e3 = __expf(s[mb][j][3]);
                if (diag) {
                    int cc = j * 8 + colb + dof;
                    if (cc     > r0l) e0 = 0.f;
                    if (cc + 1 > r0l) e1 = 0.f;
                    if (cc     > r1l) e2 = 0.f;
                    if (cc + 1 > r1l) e3 = 0.f;
                }
                s[mb][j][0] = e0; s[mb][j][1] = e1;
                s[mb][j][2] = e2; s[mb][j][3] = e3;
                rs0 += e0 + e1;
                rs1 += e2 + e3;
            }
            rs0 += __shfl_xor_sync(0xffffffffu, rs0, 1);
            rs0 += __shfl_xor_sync(0xffffffffu, rs0, 2);
            rs1 += __shfl_xor_sync(0xffffffffu, rs1, 1);
            rs1 += __shfl_xor_sync(0xffffffffu, rs1, 2);
            lsum[mb][0] += rs0;
            lsum[mb][1] += rs1;
        }

        // --- O += P V over this warp's 32 keys ---
#pragma unroll
        for (int j2 = 0; j2 < 2; j2++) {
            uint32_t ph[2][4], pl[2][4];
#pragma unroll
            for (int mb = 0; mb < 2; mb++) {
                split2(s[mb][2 * j2][0],     s[mb][2 * j2][1],     ph[mb][0], pl[mb][0]);
                split2(s[mb][2 * j2][2],     s[mb][2 * j2][3],     ph[mb][1], pl[mb][1]);
                split2(s[mb][2 * j2 + 1][0], s[mb][2 * j2 + 1][1], ph[mb][2], pl[mb][2]);
                split2(s[mb][2 * j2 + 1][2], s[mb][2 * j2 + 1][3], ph[mb][3], pl[mb][3]);
            }
#pragma unroll
            for (int d2 = 0; d2 < 8; d2++) {
                uint32_t vh[4], vl[4];
                uint32_t vaddr = vb +
                    ((kh * 32 + j2 * 16 + vbrow) * AST + d2 * 16 + vbcol) * 2;
                ldmx4t(vh, vaddr);
                ldmx4t(vl, vaddr + 17408);
#pragma unroll
                for (int mb = 0; mb < 2; mb++) {
                    mma16816(o_[mb][2 * d2],     ph[mb][0], ph[mb][1], ph[mb][2], ph[mb][3], vh[0], vh[1]);
                    mma16816(o_[mb][2 * d2],     ph[mb][0], ph[mb][1], ph[mb][2], ph[mb][3], vl[0], vl[1]);
                    mma16816(o_[mb][2 * d2],     pl[mb][0], pl[mb][1], pl[mb][2], pl[mb][3], vh[0], vh[1]);
                    mma16816(o_[mb][2 * d2 + 1], ph[mb][0], ph[mb][1], ph[mb][2], ph[mb][3], vh[2], vh[3]);
                    mma16816(o_[mb][2 * d2 + 1], ph[mb][0], ph[mb][1], ph[mb][2], ph[mb][3], vl[2], vl[3]);
                    mma16816(o_[mb][2 * d2 + 1], pl[mb][0], pl[mb][1], pl[mb][2], pl[mb][3], vh[2], vh[3]);
                }
            }
        }
        __syncthreads();
    }

    // --- combine k-half partials via smem scratch (reuse KV area) ---
    float* scr = (float*)(sm_a + 34816);       // [128][132] + lsum[128]
    float* ls  = scr + 128 * 132;
    if (kh == 1) {
#pragma unroll
        for (int mb = 0; mb < 2; mb++) {
            const int r0l = qg * 32 + mb * 16 + (lane >> 2);
            const int r1l = r0l + 8;
#pragma unroll
            for (int dn = 0; dn < 16; dn++) {
                int col = dn * 8 + colb;
                scr[r0l * 132 + col]     = o_[mb][dn][0];
                scr[r0l * 132 + col + 1] = o_[mb][dn][1];
                scr[r1l * 132 + col]     = o_[mb][dn][2];
                scr[r1l * 132 + col + 1] = o_[mb][dn][3];
            }
            if ((lane & 3) == 0) { ls[r0l] = lsum[mb][0]; ls[r1l] = lsum[mb][1]; }
        }
    }
    __syncthreads();
    if (kh == 0) {
#pragma unroll
        for (int mb = 0; mb < 2; mb++) {
            const int r0l = qg * 32 + mb * 16 + (lane >> 2);
            const int r1l = r0l + 8;
#pragma unroll
            for (int dn = 0; dn < 16; dn++) {
                int col = dn * 8 + colb;
                o_[mb][dn][0] += scr[r0l * 132 + col];
                o_[mb][dn][1] += scr[r0l * 132 + col + 1];
                o_[mb][dn][2] += scr[r1l * 132 + col];
                o_[mb][dn][3] += scr[r1l * 132 + col + 1];
            }
            float l0 = lsum[mb][0] + ls[r0l];
            float l1 = lsum[mb][1] + ls[r1l];

            if (!split_kv) {
                const float inv0 = 1.f / l0;
                const float inv1 = 1.f / l1;
                const size_t gr0 = ((size_t)b * S_LEN + q0 + r0l) * H_DIM;
                const size_t gr1 = ((size_t)b * S_LEN + q0 + r1l) * H_DIM;
#pragma unroll
                for (int dn = 0; dn < 16; dn++) {
                    int col = dn * 8 + colb;
                    *(float2*)&out[gr0 + col] = make_float2(o_[mb][dn][0] * inv0, o_[mb][dn][1] * inv0);
                    *(float2*)&out[gr1 + col] = make_float2(o_[mb][dn][2] * inv1, o_[mb][dn][3] * inv1);
                }
            } else {
                const size_t pbase = (size_t)(h * 8 + b) * 1024 + (q0 - 1024);
                float* p0 = &g_po[(pbase + r0l) * 128];
                float* p1 = &g_po[(pbase + r1l) * 128];
#pragma unroll
                for (int dn = 0; dn < 16; dn++) {
                    int col = dn * 8 + colb;
                    *(float2*)&p0[col] = make_float2(o_[mb][dn][0], o_[mb][dn][1]);
                    *(float2*)&p1[col] = make_float2(o_[mb][dn][2], o_[mb][dn][3]);
                }
                if ((lane & 3) == 0) {
                    g_pl[pbase + r0l] = l0;
                    g_pl[pbase + r1l] = l1;
                }
            }
        }
    }
}

// ---------------------------------------------------------------------------
// Kernel 3: combine split-KV partials (rows 1024..2047 of each batch)
// ---------------------------------------------------------------------------
__global__ __launch_bounds__(256)
void combine_kernel(float* __restrict__ out)
{
    int idx = blockIdx.x * 256 + threadIdx.x;
    int row = idx >> 5;
    int d4  = (idx & 31) * 4;
    int b   = row >> 10;
    int r   = row & 1023;
    float l = g_pl[(size_t)b * 1024 + r] + g_pl[(size_t)(8 + b) * 1024 + r];
    float inv = 1.f / l;
    size_t i0 = ((size_t)b * 1024 + r) * 128 + d4;
    size_t i1 = ((size_t)(8 + b) * 1024 + r) * 128 + d4;
    float4 a = *(const float4*)&g_po[i0];
    float4 c = *(const float4*)&g_po[i1];
    float4 o;
    o.x = (a.x + c.x) * inv;
    o.y = (a.y + c.y) * inv;
    o.z = (a.z + c.z) * inv;
    o.w = (a.w + c.w) * inv;
    *(float4*)&out[((size_t)b * S_LEN + 1024 + r) * H_DIM + d4] = o;
}

// ---------------------------------------------------------------------------
extern "C" void kernel_launch(void* const* d_in, const int* in_sizes, int n_in,
                              void* d_out, int out_size)
{
    const float* X    = (const float*)d_in[0];
    const float* mask = (const float*)d_in[1];
    const float* Wq   = (const float*)d_in[2];
    const float* Wk   = (const float*)d_in[3];
    const float* Wv   = (const float*)d_in[4];
    float* out        = (float*)d_out;

    split_x_kernel<<<M_TOTAL * E_DIM / 4 / 256, 256>>>(X, mask);
    split_w_kernel<<<3 * H_DIM * E_DIM / 4 / 256, 256>>>(Wq, Wk, Wv);

    cudaFuncSetAttribute(qkv_mma_kernel,
                         cudaFuncAttributeMaxDynamicSharedMemorySize, QKV_SMEM);
    dim3 g1(M_TOTAL / 128, 3);
    qkv_mma_kernel<<<g1, 128, QKV_SMEM>>>();

    cudaFuncSetAttribute(attn_mma_kernel,
                         cudaFuncAttributeMaxDynamicSharedMemorySize, ATT_SMEM);
    dim3 g2(24, B_SZ);
    attn_mma_kernel<<<g2, 256, ATT_SMEM>>>(out);

    combine_kernel<<<1024, 256>>>(out);
}

// round 15
// speedup vs baseline: 1.3905x; 1.3720x over previous
#include <cuda_runtime.h>
#include <cuda_bf16.h>
#include <cuda_fp16.h>
#include <cstdint>

#define B_SZ   8
#define S_LEN  2048
#define E_DIM  768
#define H_DIM  128
#define M_TOTAL (B_SZ * S_LEN)

// hi/lo bf16 split inputs for the (accuracy-critical) projection
__device__ __nv_bfloat16 g_xh[M_TOTAL * E_DIM];
__device__ __nv_bfloat16 g_xl[M_TOTAL * E_DIM];
__device__ __nv_bfloat16 g_wh[3 * H_DIM * E_DIM];
__device__ __nv_bfloat16 g_wl[3 * H_DIM * E_DIM];
// single-fp16 q (pre-scaled by 1/sqrt(128)), k, v for attention
__device__ __half g_qf[M_TOTAL * H_DIM];
__device__ __half g_kf[M_TOTAL * H_DIM];
__device__ __half g_vf[M_TOTAL * H_DIM];
// split-KV partials (rows 1024..2047 of each batch)
__device__ float g_po[2 * 8 * 1024 * 128];
__device__ float g_pl[2 * 8 * 1024];

// ---------------------------------------------------------------------------
// helpers (baseline PTX only: mma.sync + ldmatrix + cp.async)
// ---------------------------------------------------------------------------
__device__ __forceinline__ uint32_t smem_u32(const void* p) {
    uint32_t a;
    asm("{ .reg .u64 t; cvta.to.shared.u64 t, %1; cvt.u32.u64 %0, t; }"
        : "=r"(a) : "l"(p));
    return a;
}
__device__ __forceinline__ void mma16816(float c[4],
                                         uint32_t a0, uint32_t a1, uint32_t a2, uint32_t a3,
                                         uint32_t b0, uint32_t b1) {
    asm volatile(
        "mma.sync.aligned.m16n8k16.row.col.f32.bf16.bf16.f32 "
        "{%0,%1,%2,%3}, {%4,%5,%6,%7}, {%8,%9}, {%0,%1,%2,%3};"
        : "+f"(c[0]), "+f"(c[1]), "+f"(c[2]), "+f"(c[3])
        : "r"(a0), "r"(a1), "r"(a2), "r"(a3), "r"(b0), "r"(b1));
}
__device__ __forceinline__ void mma16816f(float c[4],
                                          uint32_t a0, uint32_t a1, uint32_t a2, uint32_t a3,
                                          uint32_t b0, uint32_t b1) {
    asm volatile(
        "mma.sync.aligned.m16n8k16.row.col.f32.f16.f16.f32 "
        "{%0,%1,%2,%3}, {%4,%5,%6,%7}, {%8,%9}, {%0,%1,%2,%3};"
        : "+f"(c[0]), "+f"(c[1]), "+f"(c[2]), "+f"(c[3])
        : "r"(a0), "r"(a1), "r"(a2), "r"(a3), "r"(b0), "r"(b1));
}
__device__ __forceinline__ void ldmx4(uint32_t r[4], uint32_t addr) {
    asm volatile("ldmatrix.sync.aligned.m8n8.x4.shared.b16 {%0,%1,%2,%3}, [%4];"
                 : "=r"(r[0]), "=r"(r[1]), "=r"(r[2]), "=r"(r[3]) : "r"(addr));
}
__device__ __forceinline__ void ldmx4t(uint32_t r[4], uint32_t addr) {
    asm volatile("ldmatrix.sync.aligned.m8n8.x4.trans.shared.b16 {%0,%1,%2,%3}, [%4];"
                 : "=r"(r[0]), "=r"(r[1]), "=r"(r[2]), "=r"(r[3]) : "r"(addr));
}
__device__ __forceinline__ void cp16(uint32_t s, const void* g) {
    asm volatile("cp.async.cg.shared.global [%0], [%1], 16;" :: "r"(s), "l"(g));
}
#define CP_COMMIT()  asm volatile("cp.async.commit_group;" ::: "memory")
#define CP_WAIT1()   asm volatile("cp.async.wait_group 1;" ::: "memory")
#define CP_WAIT0()   asm volatile("cp.async.wait_group 0;" ::: "memory")

// hi/lo bf16 split of two floats packed bf16x2 (first value in low half)
__device__ __forceinline__ void split2(float a, float b, uint32_t& hi, uint32_t& lo) {
    __nv_bfloat16 ah = __float2bfloat16(a);
    __nv_bfloat16 bh = __float2bfloat16(b);
    __nv_bfloat16 al = __float2bfloat16(a - __bfloat162float(ah));
    __nv_bfloat16 bl = __float2bfloat16(b - __bfloat162float(bh));
    hi = ((uint32_t)__bfloat16_as_ushort(bh) << 16) | (uint32_t)__bfloat16_as_ushort(ah);
    lo = ((uint32_t)__bfloat16_as_ushort(bl) << 16) | (uint32_t)__bfloat16_as_ushort(al);
}
// pack two floats to fp16x2 (first value in low half)
__device__ __forceinline__ uint32_t packh2(float a, float b) {
    __half2 h = __floats2half2_rn(a, b);
    return *(uint32_t*)&h;
}

// ---------------------------------------------------------------------------
// Kernel 0a/0b: one-time hi/lo splits (memory-bound)
// ---------------------------------------------------------------------------
__global__ __launch_bounds__(256)
void split_x_kernel(const float* __restrict__ X, const float* __restrict__ mask)
{
    int idx = (blockIdx.x * 256 + threadIdx.x) * 4;
    float mk = mask[idx / E_DIM];
    float4 v = *(const float4*)&X[idx];
    uint32_t h0, l0, h1, l1;
    split2(v.x * mk, v.y * mk, h0, l0);
    split2(v.z * mk, v.w * mk, h1, l1);
    *(uint2*)&g_xh[idx] = make_uint2(h0, h1);
    *(uint2*)&g_xl[idx] = make_uint2(l0, l1);
}
__global__ __launch_bounds__(256)
void split_w_kernel(const float* __restrict__ Wq, const float* __restrict__ Wk,
                    const float* __restrict__ Wv)
{
    int idx = (blockIdx.x * 256 + threadIdx.x) * 4;
    int o = idx / (H_DIM * E_DIM);
    int r = idx - o * (H_DIM * E_DIM);
    const float* W = (o == 0) ? Wq : (o == 1 ? Wk : Wv);
    float4 v = *(const float4*)&W[r];
    uint32_t h0, l0, h1, l1;
    split2(v.x, v.y, h0, l0);
    split2(v.z, v.w, h1, l1);
    *(uint2*)&g_wh[idx] = make_uint2(h0, h1);
    *(uint2*)&g_wl[idx] = make_uint2(l0, l1);
}

// ---------------------------------------------------------------------------
// Kernel 1: QKV projection, bf16x3 warp MMA, cp.async double-buffered.
// grid=(128,3), block=128 (4 warps, each 32 m-rows x 128 n).  BM=128, BK=32.
// Epilogue emits single fp16 q (pre-scaled), k, v.
// ---------------------------------------------------------------------------
#define QAST 40
#define QSTG 20480
#define QKV_SMEM (2 * 40960)

__global__ __launch_bounds__(128, 2)
void qkv_mma_kernel()
{
    extern __shared__ __align__(16) __nv_bfloat16 sm_q[];
    const int tid  = threadIdx.x;
    const int lane = tid & 31;
    const int wid  = tid >> 5;
    const int m0   = blockIdx.x * 128;
    const int o    = blockIdx.y;
    const size_t wbase = (size_t)o * H_DIM * E_DIM;

    float c[2][16][4];
#pragma unroll
    for (int mb = 0; mb < 2; mb++)
#pragma unroll
        for (int j = 0; j < 16; j++)
#pragma unroll
            for (int i = 0; i < 4; i++) c[mb][j][i] = 0.f;

    auto issue = [&](int cc, int s) {
        uint32_t sb = smem_u32(sm_q + s * QSTG);
        const int k0 = cc * 32;
#pragma unroll
        for (int i = 0; i < 4; i++) {
            int idx = tid + i * 128;          // 0..511: X 128 rows x 4 chunks16
            int row = idx >> 2, c16 = idx & 3;
            size_t g = (size_t)(m0 + row) * E_DIM + k0 + c16 * 8;
            uint32_t d = sb + (row * QAST + c16 * 8) * 2;
            cp16(d,         &g_xh[g]);
            cp16(d + 10240, &g_xl[g]);
        }
#pragma unroll
        for (int i = 0; i < 4; i++) {
            int idx = tid + i * 128;          // 0..511: W 128 rows x 4 chunks16
            int row = idx >> 2, c16 = idx & 3;
            size_t g = wbase + (size_t)row * E_DIM + k0 + c16 * 8;
            uint32_t d = sb + (10240 + row * QAST + c16 * 8) * 2;
            cp16(d,         &g_wh[g]);
            cp16(d + 10240, &g_wl[g]);
        }
    };

    issue(0, 0); CP_COMMIT();

    const int brow = ((lane >> 4) & 1) * 8 + (lane & 7);
    const int bcol = ((lane >> 3) & 1) * 8;

    for (int cc = 0; cc < 24; cc++) {
        if (cc < 23) { issue(cc + 1, (cc + 1) & 1); CP_COMMIT(); CP_WAIT1(); }
        else CP_WAIT0();
        __syncthreads();

        const uint32_t xh_base = smem_u32(sm_q + (cc & 1) * QSTG);
        const uint32_t wh_base = xh_base + 20480;
#pragma unroll
        for (int kd = 0; kd < 2; kd++) {
            uint32_t ah[2][4], al[2][4];
#pragma unroll
            for (int mb = 0; mb < 2; mb++) {
                uint32_t aaddr = xh_base +
                    ((wid * 32 + mb * 16 + (lane & 15)) * QAST + kd * 16 +
                     ((lane >> 4) << 3)) * 2;
                ldmx4(ah[mb], aaddr);
                ldmx4(al[mb], aaddr + 10240);
            }
#pragma unroll
            for (int jp = 0; jp < 8; jp++) {
                uint32_t bh[4], bl[4];
                uint32_t baddr = wh_base +
                    ((jp * 16 + brow) * QAST + kd * 16 + bcol) * 2;
                ldmx4(bh, baddr);
                ldmx4(bl, baddr + 10240);
#pragma unroll
                for (int mb = 0; mb < 2; mb++) {
                    mma16816(c[mb][2 * jp],     ah[mb][0], ah[mb][1], ah[mb][2], ah[mb][3], bh[0], bh[1]);
                    mma16816(c[mb][2 * jp],     ah[mb][0], ah[mb][1], ah[mb][2], ah[mb][3], bl[0], bl[1]);
                    mma16816(c[mb][2 * jp],     al[mb][0], al[mb][1], al[mb][2], al[mb][3], bh[0], bh[1]);
                    mma16816(c[mb][2 * jp + 1], ah[mb][0], ah[mb][1], ah[mb][2], ah[mb][3], bh[2], bh[3]);
                    mma16816(c[mb][2 * jp + 1], ah[mb][0], ah[mb][1], ah[mb][2], ah[mb][3], bl[2], bl[3]);
                    mma16816(c[mb][2 * jp + 1], al[mb][0], al[mb][1], al[mb][2], al[mb][3], bh[2], bh[3]);
                }
            }
        }
        __syncthreads();
    }

    const float sc = (o == 0) ? 0.0883883476483184f : 1.f;   // 1/sqrt(128) on q
    __half* of = (o == 0) ? g_qf : (o == 1 ? g_kf : g_vf);
#pragma unroll
    for (int mb = 0; mb < 2; mb++) {
        const size_t r0 = (size_t)(m0 + wid * 32 + mb * 16 + (lane >> 2)) * H_DIM;
        const size_t r1 = r0 + 8 * H_DIM;
#pragma unroll
        for (int j = 0; j < 16; j++) {
            int col = j * 8 + (lane & 3) * 2;
            *(uint32_t*)&of[r0 + col] = packh2(c[mb][j][0] * sc, c[mb][j][1] * sc);
            *(uint32_t*)&of[r1 + col] = packh2(c[mb][j][2] * sc, c[mb][j][3] * sc);
        }
    }
}

// ---------------------------------------------------------------------------
// Kernel 2: causal flash attention, single-fp16 MMA (1 MMA per logical GEMM).
// QT=128, KT=64, block=256 (8 warps, each 16q x 64k).
// grid=(24,8): bx<16 -> split-KV halves for qt=15-(bx>>1); bx>=16 -> qt=23-bx.
// smem (half elems, stride 136): Qf 0 (128 rows); KV stage s @ 17408+s*17408:
//   Kf +0 (64 rows), Vf +8704.  Total 104448 B -> 2 CTAs/SM, one wave.
// ---------------------------------------------------------------------------
#define AST 136
#define KVSTG_E 17408
#define ATT_SMEM 104448

__global__ __launch_bounds__(256, 2)
void attn_mma_kernel(float* __restrict__ out)
{
    extern __shared__ __align__(16) __half sm_a[];

    const int tid  = threadIdx.x;
    const int lane = tid & 31;
    const int wid  = tid >> 5;
    const int b    = blockIdx.y;
    const int bx   = blockIdx.x;

    int qt, h, sbeg, send;
    bool split_kv;
    if (bx < 16) {
        split_kv = true;
        qt   = 15 - (bx >> 1);
        h    = bx & 1;
        sbeg = h * (qt + 1);
        send = sbeg + qt + 1;
    } else {
        split_kv = false;
        qt   = 23 - bx;
        h    = 0;
        sbeg = 0;
        send = 2 * qt + 2;
    }
    const int q0 = qt * 128;

    const uint32_t qh_base = smem_u32(sm_a);

    auto issue_kv = [&](int kts, int s) {
        uint32_t kb = smem_u32(sm_a + 17408 + s * KVSTG_E);
#pragma unroll
        for (int i = 0; i < 4; i++) {
            int idx = tid + i * 256;           // 0..1023: 64 rows x 16 chunks
            int row = idx >> 4, c8 = idx & 15;
            size_t g = ((size_t)b * S_LEN + kts * 64 + row) * H_DIM + c8 * 8;
            uint32_t d = kb + (row * AST + c8 * 8) * 2;
            cp16(d,         &g_kf[g]);
            cp16(d + 17408, &g_vf[g]);
        }
    };

    issue_kv(sbeg, sbeg & 1); CP_COMMIT();

    // --- stage Q (fp16), 128 rows ---
#pragma unroll
    for (int i = 0; i < 8; i++) {
        int idx = tid + i * 256;               // 0..2047
        int row = idx >> 4, c8 = idx & 15;
        size_t g = ((size_t)b * S_LEN + q0 + row) * H_DIM + c8 * 8;
        *(uint4*)&sm_a[row * AST + c8 * 8] = *(const uint4*)&g_qf[g];
    }

    float o_[16][4];
#pragma unroll
    for (int d = 0; d < 16; d++)
#pragma unroll
        for (int i = 0; i < 4; i++) o_[d][i] = 0.f;
    float lsum0 = 0.f, lsum1 = 0.f;

    const int colb = (lane & 3) * 2;
    const int r0l  = wid * 16 + (lane >> 2);
    const int r1l  = r0l + 8;
    const int kbrow = ((lane >> 4) & 1) * 8 + (lane & 7);
    const int kbcol = ((lane >> 3) & 1) * 8;
    const int vbrow = ((lane >> 3) & 1) * 8 + (lane & 7);
    const int vbcol = ((lane >> 4) & 1) * 8;

    for (int kts = sbeg; kts < send; kts++) {
        if (kts + 1 < send) { issue_kv(kts + 1, (kts + 1) & 1); CP_COMMIT(); CP_WAIT1(); }
        else CP_WAIT0();
        __syncthreads();

        const uint32_t kb = smem_u32(sm_a + 17408 + (kts & 1) * KVSTG_E);
        const uint32_t vb = kb + 17408;        // Vf bytes

        // --- S = Q K^T  (this warp: 16 q x 64 k, single fp16 MMA) ---
        float s[8][4];
#pragma unroll
        for (int j = 0; j < 8; j++)
#pragma unroll
            for (int i = 0; i < 4; i++) s[j][i] = 0.f;

#pragma unroll
        for (int kd = 0; kd < 8; kd++) {
            uint32_t ah[4];
            uint32_t aaddr = qh_base +
                ((wid * 16 + (lane & 15)) * AST + kd * 16 + ((lane >> 4) << 3)) * 2;
            ldmx4(ah, aaddr);
#pragma unroll
            for (int jp = 0; jp < 4; jp++) {
                uint32_t bh[4];
                uint32_t baddr = kb + ((jp * 16 + kbrow) * AST + kd * 16 + kbcol) * 2;
                ldmx4(bh, baddr);
                mma16816f(s[2 * jp],     ah[0], ah[1], ah[2], ah[3], bh[0], bh[1]);
                mma16816f(s[2 * jp + 1], ah[0], ah[1], ah[2], ah[3], bh[2], bh[3]);
            }
        }

        // --- exp (+ causal mask), row sums ---
        const bool diag = (kts >= 2 * qt);
        const int dof = kts * 64 - q0;
        float rs0 = 0.f, rs1 = 0.f;
#pragma unroll
        for (int j = 0; j < 8; j++) {
            float e0 = __expf(s[j][0]);
            float e1 = __expf(s[j][1]);
            float e2 = __expf(s[j][2]);
            float e3 = __expf(s[j][3]);
            if (diag) {
                int cc = j * 8 + colb + dof;
                if (cc     > r0l) e0 = 0.f;
                if (cc + 1 > r0l) e1 = 0.f;
                if (cc     > r1l) e2 = 0.f;
                if (cc + 1 > r1l) e3 = 0.f;
            }
            s[j][0] = e0; s[j][1] = e1; s[j][2] = e2; s[j][3] = e3;
            rs0 += e0 + e1;
            rs1 += e2 + e3;
        }
        rs0 += __shfl_xor_sync(0xffffffffu, rs0, 1);
        rs0 += __shfl_xor_sync(0xffffffffu, rs0, 2);
        rs1 += __shfl_xor_sync(0xffffffffu, rs1, 1);
        rs1 += __shfl_xor_sync(0xffffffffu, rs1, 2);
        lsum0 += rs0;
        lsum1 += rs1;

        // --- O += P V (P fp16 A-frags in-register, single MMA) ---
#pragma unroll
        for (int j2 = 0; j2 < 4; j2++) {
            uint32_t ph[4];
            ph[0] = packh2(s[2 * j2][0],     s[2 * j2][1]);
            ph[1] = packh2(s[2 * j2][2],     s[2 * j2][3]);
            ph[2] = packh2(s[2 * j2 + 1][0], s[2 * j2 + 1][1]);
            ph[3] = packh2(s[2 * j2 + 1][2], s[2 * j2 + 1][3]);
#pragma unroll
            for (int d2 = 0; d2 < 8; d2++) {
                uint32_t vh[4];
                uint32_t vaddr = vb + ((j2 * 16 + vbrow) * AST + d2 * 16 + vbcol) * 2;
                ldmx4t(vh, vaddr);
                mma16816f(o_[2 * d2],     ph[0], ph[1], ph[2], ph[3], vh[0], vh[1]);
                mma16816f(o_[2 * d2 + 1], ph[0], ph[1], ph[2], ph[3], vh[2], vh[3]);
            }
        }
        __syncthreads();
    }

    // --- epilogue ---
    if (!split_kv) {
        const float inv0 = 1.f / lsum0;
        const float inv1 = 1.f / lsum1;
        const size_t gr0 = ((size_t)b * S_LEN + q0 + r0l) * H_DIM;
        const size_t gr1 = gr0 + 8 * H_DIM;
#pragma unroll
        for (int dn = 0; dn < 16; dn++) {
            int col = dn * 8 + colb;
            *(float2*)&out[gr0 + col] = make_float2(o_[dn][0] * inv0, o_[dn][1] * inv0);
            *(float2*)&out[gr1 + col] = make_float2(o_[dn][2] * inv1, o_[dn][3] * inv1);
        }
    } else {
        const size_t pbase = (size_t)(h * 8 + b) * 1024 + (q0 - 1024);
        float* p0 = &g_po[(pbase + r0l) * 128];
        float* p1 = &g_po[(pbase + r1l) * 128];
#pragma unroll
        for (int dn = 0; dn < 16; dn++) {
            int col = dn * 8 + colb;
            *(float2*)&p0[col] = make_float2(o_[dn][0], o_[dn][1]);
            *(float2*)&p1[col] = make_float2(o_[dn][2], o_[dn][3]);
        }
        if ((lane & 3) == 0) {
            g_pl[pbase + r0l] = lsum0;
            g_pl[pbase + r1l] = lsum1;
        }
    }
}

// ---------------------------------------------------------------------------
// Kernel 3: combine split-KV partials (rows 1024..2047 of each batch)
// ---------------------------------------------------------------------------
__global__ __launch_bounds__(256)
void combine_kernel(float* __restrict__ out)
{
    int idx = blockIdx.x * 256 + threadIdx.x;
    int row = idx >> 5;
    int d4  = (idx & 31) * 4;
    int b   = row >> 10;
    int r   = row & 1023;
    float l = g_pl[(size_t)b * 1024 + r] + g_pl[(size_t)(8 + b) * 1024 + r];
    float inv = 1.f / l;
    size_t i0 = ((size_t)b * 1024 + r) * 128 + d4;
    size_t i1 = ((size_t)(8 + b) * 1024 + r) * 128 + d4;
    float4 a = *(const float4*)&g_po[i0];
    float4 c = *(const float4*)&g_po[i1];
    float4 o;
    o.x = (a.x + c.x) * inv;
    o.y = (a.y + c.y) * inv;
    o.z = (a.z + c.z) * inv;
    o.w = (a.w + c.w) * inv;
    *(float4*)&out[((size_t)b * S_LEN + 1024 + r) * H_DIM + d4] = o;
}

// ---------------------------------------------------------------------------
extern "C" void kernel_launch(void* const* d_in, const int* in_sizes, int n_in,
                              void* d_out, int out_size)
{
    const float* X    = (const float*)d_in[0];
    const float* mask = (const float*)d_in[1];
    const float* Wq   = (const float*)d_in[2];
    const float* Wk   = (const float*)d_in[3];
    const float* Wv   = (const float*)d_in[4];
    float* out        = (float*)d_out;

    split_x_kernel<<<M_TOTAL * E_DIM / 4 / 256, 256>>>(X, mask);
    split_w_kernel<<<3 * H_DIM * E_DIM / 4 / 256, 256>>>(Wq, Wk, Wv);

    cudaFuncSetAttribute(qkv_mma_kernel,
                         cudaFuncAttributeMaxDynamicSharedMemorySize, QKV_SMEM);
    dim3 g1(M_TOTAL / 128, 3);
    qkv_mma_kernel<<<g1, 128, QKV_SMEM>>>();

    cudaFuncSetAttribute(attn_mma_kernel,
                         cudaFuncAttributeMaxDynamicSharedMemorySize, ATT_SMEM);
    dim3 g2(24, B_SZ);
    attn_mma_kernel<<<g2, 256, ATT_SMEM>>>(out);

    combine_kernel<<<1024, 256>>>(out);
}

// round 16
// speedup vs baseline: 1.6968x; 1.2203x over previous
#include <cuda_runtime.h>
#include <cuda_bf16.h>
#include <cuda_fp16.h>
#include <cstdint>

#define B_SZ   8
#define S_LEN  2048
#define E_DIM  768
#define H_DIM  128
#define M_TOTAL (B_SZ * S_LEN)

// fp16 inputs for the projection: X single, W hi/lo (exact to ~18 bits)
__device__ __half g_xf[M_TOTAL * E_DIM];
__device__ __half g_wfh[3 * H_DIM * E_DIM];
__device__ __half g_wfl[3 * H_DIM * E_DIM];
// single-fp16 q (pre-scaled by 1/sqrt(128)), k, v for attention
__device__ __half g_qf[M_TOTAL * H_DIM];
__device__ __half g_kf[M_TOTAL * H_DIM];
__device__ __half g_vf[M_TOTAL * H_DIM];
// split-KV partials (rows 1024..2047 of each batch)
__device__ float g_po[2 * 8 * 1024 * 128];
__device__ float g_pl[2 * 8 * 1024];

// ---------------------------------------------------------------------------
// helpers (baseline PTX only: mma.sync + ldmatrix + cp.async)
// ---------------------------------------------------------------------------
__device__ __forceinline__ uint32_t smem_u32(const void* p) {
    uint32_t a;
    asm("{ .reg .u64 t; cvta.to.shared.u64 t, %1; cvt.u32.u64 %0, t; }"
        : "=r"(a) : "l"(p));
    return a;
}
__device__ __forceinline__ void mma16816f(float c[4],
                                          uint32_t a0, uint32_t a1, uint32_t a2, uint32_t a3,
                                          uint32_t b0, uint32_t b1) {
    asm volatile(
        "mma.sync.aligned.m16n8k16.row.col.f32.f16.f16.f32 "
        "{%0,%1,%2,%3}, {%4,%5,%6,%7}, {%8,%9}, {%0,%1,%2,%3};"
        : "+f"(c[0]), "+f"(c[1]), "+f"(c[2]), "+f"(c[3])
        : "r"(a0), "r"(a1), "r"(a2), "r"(a3), "r"(b0), "r"(b1));
}
__device__ __forceinline__ void ldmx4(uint32_t r[4], uint32_t addr) {
    asm volatile("ldmatrix.sync.aligned.m8n8.x4.shared.b16 {%0,%1,%2,%3}, [%4];"
                 : "=r"(r[0]), "=r"(r[1]), "=r"(r[2]), "=r"(r[3]) : "r"(addr));
}
__device__ __forceinline__ void ldmx4t(uint32_t r[4], uint32_t addr) {
    asm volatile("ldmatrix.sync.aligned.m8n8.x4.trans.shared.b16 {%0,%1,%2,%3}, [%4];"
                 : "=r"(r[0]), "=r"(r[1]), "=r"(r[2]), "=r"(r[3]) : "r"(addr));
}
__device__ __forceinline__ void cp16(uint32_t s, const void* g) {
    asm volatile("cp.async.cg.shared.global [%0], [%1], 16;" :: "r"(s), "l"(g));
}
#define CP_COMMIT()  asm volatile("cp.async.commit_group;" ::: "memory")
#define CP_WAIT1()   asm volatile("cp.async.wait_group 1;" ::: "memory")
#define CP_WAIT0()   asm volatile("cp.async.wait_group 0;" ::: "memory")

// pack two floats to fp16x2 (first value in low half)
__device__ __forceinline__ uint32_t packh2(float a, float b) {
    __half2 h = __floats2half2_rn(a, b);
    return *(uint32_t*)&h;
}
// fp16 hi/lo split of two floats packed fp16x2
__device__ __forceinline__ void splith2(float a, float b, uint32_t& hi, uint32_t& lo) {
    __half ah = __float2half_rn(a);
    __half bh = __float2half_rn(b);
    __half al = __float2half_rn(a - __half2float(ah));
    __half bl = __float2half_rn(b - __half2float(bh));
    hi = ((uint32_t)__half_as_ushort(bh) << 16) | (uint32_t)__half_as_ushort(ah);
    lo = ((uint32_t)__half_as_ushort(bl) << 16) | (uint32_t)__half_as_ushort(al);
}

// ---------------------------------------------------------------------------
// Kernel 0a/0b: one-time conversions (memory-bound)
// ---------------------------------------------------------------------------
__global__ __launch_bounds__(256)
void split_x_kernel(const float* __restrict__ X, const float* __restrict__ mask)
{
    int idx = (blockIdx.x * 256 + threadIdx.x) * 4;
    float mk = mask[idx / E_DIM];
    float4 v = *(const float4*)&X[idx];
    uint2 o;
    o.x = packh2(v.x * mk, v.y * mk);
    o.y = packh2(v.z * mk, v.w * mk);
    *(uint2*)&g_xf[idx] = o;
}
__global__ __launch_bounds__(256)
void split_w_kernel(const float* __restrict__ Wq, const float* __restrict__ Wk,
                    const float* __restrict__ Wv)
{
    int idx = (blockIdx.x * 256 + threadIdx.x) * 4;
    int o = idx / (H_DIM * E_DIM);
    int r = idx - o * (H_DIM * E_DIM);
    const float* W = (o == 0) ? Wq : (o == 1 ? Wk : Wv);
    float4 v = *(const float4*)&W[r];
    uint32_t h0, l0, h1, l1;
    splith2(v.x, v.y, h0, l0);
    splith2(v.z, v.w, h1, l1);
    *(uint2*)&g_wfh[idx] = make_uint2(h0, h1);
    *(uint2*)&g_wfl[idx] = make_uint2(l0, l1);
}

// ---------------------------------------------------------------------------
// Kernel 1: QKV projection, fp16 2-MMA (X single, W hi/lo), cp.async
// double-buffered.  grid=(128,3), block=128 (4 warps x 32 m-rows), BM=128,
// BK=32.  Stage (half elems, stride 40): Xf 0, Wh 5120, Wl 10240; 15360
// elems = 30720 B per stage x2 = 61440 B -> 3 CTAs/SM.
// ---------------------------------------------------------------------------
#define QAST 40
#define QSTG 15360
#define QKV_SMEM (2 * 30720)

__global__ __launch_bounds__(128, 3)
void qkv_mma_kernel()
{
    extern __shared__ __align__(16) __half sm_q[];
    const int tid  = threadIdx.x;
    const int lane = tid & 31;
    const int wid  = tid >> 5;
    const int m0   = blockIdx.x * 128;
    const int o    = blockIdx.y;
    const size_t wbase = (size_t)o * H_DIM * E_DIM;

    float c[2][16][4];
#pragma unroll
    for (int mb = 0; mb < 2; mb++)
#pragma unroll
        for (int j = 0; j < 16; j++)
#pragma unroll
            for (int i = 0; i < 4; i++) c[mb][j][i] = 0.f;

    auto issue = [&](int cc, int s) {
        uint32_t sb = smem_u32(sm_q + s * QSTG);
        const int k0 = cc * 32;
#pragma unroll
        for (int i = 0; i < 4; i++) {
            int idx = tid + i * 128;          // 0..511: X 128 rows x 4 chunks16
            int row = idx >> 2, c16 = idx & 3;
            size_t g = (size_t)(m0 + row) * E_DIM + k0 + c16 * 8;
            cp16(sb + (row * QAST + c16 * 8) * 2, &g_xf[g]);
        }
#pragma unroll
        for (int i = 0; i < 4; i++) {
            int idx = tid + i * 128;          // 0..511: W 128 rows x 4 chunks16
            int row = idx >> 2, c16 = idx & 3;
            size_t g = wbase + (size_t)row * E_DIM + k0 + c16 * 8;
            uint32_t d = sb + 10240 + (row * QAST + c16 * 8) * 2;
            cp16(d,         &g_wfh[g]);
            cp16(d + 10240, &g_wfl[g]);
        }
    };

    issue(0, 0); CP_COMMIT();

    const int brow = ((lane >> 4) & 1) * 8 + (lane & 7);
    const int bcol = ((lane >> 3) & 1) * 8;

    for (int cc = 0; cc < 24; cc++) {
        if (cc < 23) { issue(cc + 1, (cc + 1) & 1); CP_COMMIT(); CP_WAIT1(); }
        else CP_WAIT0();
        __syncthreads();

        const uint32_t xf_base = smem_u32(sm_q + (cc & 1) * QSTG);
        const uint32_t wh_base = xf_base + 10240;
#pragma unroll
        for (int kd = 0; kd < 2; kd++) {
            uint32_t ah[2][4];
#pragma unroll
            for (int mb = 0; mb < 2; mb++) {
                uint32_t aaddr = xf_base +
                    ((wid * 32 + mb * 16 + (lane & 15)) * QAST + kd * 16 +
                     ((lane >> 4) << 3)) * 2;
                ldmx4(ah[mb], aaddr);
            }
#pragma unroll
            for (int jp = 0; jp < 8; jp++) {
                uint32_t bh[4], bl[4];
                uint32_t baddr = wh_base +
                    ((jp * 16 + brow) * QAST + kd * 16 + bcol) * 2;
                ldmx4(bh, baddr);
                ldmx4(bl, baddr + 10240);
#pragma unroll
                for (int mb = 0; mb < 2; mb++) {
                    mma16816f(c[mb][2 * jp],     ah[mb][0], ah[mb][1], ah[mb][2], ah[mb][3], bh[0], bh[1]);
                    mma16816f(c[mb][2 * jp],     ah[mb][0], ah[mb][1], ah[mb][2], ah[mb][3], bl[0], bl[1]);
                    mma16816f(c[mb][2 * jp + 1], ah[mb][0], ah[mb][1], ah[mb][2], ah[mb][3], bh[2], bh[3]);
                    mma16816f(c[mb][2 * jp + 1], ah[mb][0], ah[mb][1], ah[mb][2], ah[mb][3], bl[2], bl[3]);
                }
            }
        }
        __syncthreads();
    }

    const float sc = (o == 0) ? 0.0883883476483184f : 1.f;   // 1/sqrt(128) on q
    __half* of = (o == 0) ? g_qf : (o == 1 ? g_kf : g_vf);
#pragma unroll
    for (int mb = 0; mb < 2; mb++) {
        const size_t r0 = (size_t)(m0 + wid * 32 + mb * 16 + (lane >> 2)) * H_DIM;
        const size_t r1 = r0 + 8 * H_DIM;
#pragma unroll
        for (int j = 0; j < 16; j++) {
            int col = j * 8 + (lane & 3) * 2;
            *(uint32_t*)&of[r0 + col] = packh2(c[mb][j][0] * sc, c[mb][j][1] * sc);
            *(uint32_t*)&of[r1 + col] = packh2(c[mb][j][2] * sc, c[mb][j][3] * sc);
        }
    }
}

// ---------------------------------------------------------------------------
// Kernel 2: causal flash attention, single-fp16 MMA (validated in R15).
// QT=128, KT=64, block=256 (8 warps, each 16q x 64k).
// grid=(24,8): bx<16 -> split-KV halves for qt=15-(bx>>1); bx>=16 -> qt=23-bx.
// smem (half elems, stride 136): Qf 0 (128 rows); KV stage s @ 17408+s*17408:
//   Kf +0 (64 rows), Vf +8704.  Total 104448 B -> 2 CTAs/SM, one wave.
// ---------------------------------------------------------------------------
#define AST 136
#define KVSTG_E 17408
#define ATT_SMEM 104448

__global__ __launch_bounds__(256, 2)
void attn_mma_kernel(float* __restrict__ out)
{
    extern __shared__ __align__(16) __half sm_a[];

    const int tid  = threadIdx.x;
    const int lane = tid & 31;
    const int wid  = tid >> 5;
    const int b    = blockIdx.y;
    const int bx   = blockIdx.x;

    int qt, h, sbeg, send;
    bool split_kv;
    if (bx < 16) {
        split_kv = true;
        qt   = 15 - (bx >> 1);
        h    = bx & 1;
        sbeg = h * (qt + 1);
        send = sbeg + qt + 1;
    } else {
        split_kv = false;
        qt   = 23 - bx;
        h    = 0;
        sbeg = 0;
        send = 2 * qt + 2;
    }
    const int q0 = qt * 128;

    const uint32_t qh_base = smem_u32(sm_a);

    auto issue_kv = [&](int kts, int s) {
        uint32_t kb = smem_u32(sm_a + 17408 + s * KVSTG_E);
#pragma unroll
        for (int i = 0; i < 4; i++) {
            int idx = tid + i * 256;           // 0..1023: 64 rows x 16 chunks
            int row = idx >> 4, c8 = idx & 15;
            size_t g = ((size_t)b * S_LEN + kts * 64 + row) * H_DIM + c8 * 8;
            uint32_t d = kb + (row * AST + c8 * 8) * 2;
            cp16(d,         &g_kf[g]);
            cp16(d + 17408, &g_vf[g]);
        }
    };

    issue_kv(sbeg, sbeg & 1); CP_COMMIT();

    // --- stage Q (fp16), 128 rows ---
#pragma unroll
    for (int i = 0; i < 8; i++) {
        int idx = tid + i * 256;               // 0..2047
        int row = idx >> 4, c8 = idx & 15;
        size_t g = ((size_t)b * S_LEN + q0 + row) * H_DIM + c8 * 8;
        *(uint4*)&sm_a[row * AST + c8 * 8] = *(const uint4*)&g_qf[g];
    }

    float o_[16][4];
#pragma unroll
    for (int d = 0; d < 16; d++)
#pragma unroll
        for (int i = 0; i < 4; i++) o_[d][i] = 0.f;
    float lsum0 = 0.f, lsum1 = 0.f;

    const int colb = (lane & 3) * 2;
    const int r0l  = wid * 16 + (lane >> 2);
    const int r1l  = r0l + 8;
    const int kbrow = ((lane >> 4) & 1) * 8 + (lane & 7);
    const int kbcol = ((lane >> 3) & 1) * 8;
    const int vbrow = ((lane >> 3) & 1) * 8 + (lane & 7);
    const int vbcol = ((lane >> 4) & 1) * 8;

    for (int kts = sbeg; kts < send; kts++) {
        if (kts + 1 < send) { issue_kv(kts + 1, (kts + 1) & 1); CP_COMMIT(); CP_WAIT1(); }
        else CP_WAIT0();
        __syncthreads();

        const uint32_t kb = smem_u32(sm_a + 17408 + (kts & 1) * KVSTG_E);
        const uint32_t vb = kb + 17408;        // Vf bytes

        // --- S = Q K^T  (this warp: 16 q x 64 k, single fp16 MMA) ---
        float s[8][4];
#pragma unroll
        for (int j = 0; j < 8; j++)
#pragma unroll
            for (int i = 0; i < 4; i++) s[j][i] = 0.f;

#pragma unroll
        for (int kd = 0; kd < 8; kd++) {
            uint32_t ah[4];
            uint32_t aaddr = qh_base +
                ((wid * 16 + (lane & 15)) * AST + kd * 16 + ((lane >> 4) << 3)) * 2;
            ldmx4(ah, aaddr);
#pragma unroll
            for (int jp = 0; jp < 4; jp++) {
                uint32_t bh[4];
                uint32_t baddr = kb + ((jp * 16 + kbrow) * AST + kd * 16 + kbcol) * 2;
                ldmx4(bh, baddr);
                mma16816f(s[2 * jp],     ah[0], ah[1], ah[2], ah[3], bh[0], bh[1]);
                mma16816f(s[2 * jp + 1], ah[0], ah[1], ah[2], ah[3], bh[2], bh[3]);
            }
        }

        // --- exp (+ causal mask), row sums ---
        const bool diag = (kts >= 2 * qt);
        const int dof = kts * 64 - q0;
        float rs0 = 0.f, rs1 = 0.f;
#pragma unroll
        for (int j = 0; j < 8; j++) {
            float e0 = __expf(s[j][0]);
            float e1 = __expf(s[j][1]);
            float e2 = __expf(s[j][2]);
            float e3 = __expf(s[j][3]);
            if (diag) {
                int cc = j * 8 + colb + dof;
                if (cc     > r0l) e0 = 0.f;
                if (cc + 1 > r0l) e1 = 0.f;
                if (cc     > r1l) e2 = 0.f;
                if (cc + 1 > r1l) e3 = 0.f;
            }
            s[j][0] = e0; s[j][1] = e1; s[j][2] = e2; s[j][3] = e3;
            rs0 += e0 + e1;
            rs1 += e2 + e3;
        }
        rs0 += __shfl_xor_sync(0xffffffffu, rs0, 1);
        rs0 += __shfl_xor_sync(0xffffffffu, rs0, 2);
        rs1 += __shfl_xor_sync(0xffffffffu, rs1, 1);
        rs1 += __shfl_xor_sync(0xffffffffu, rs1, 2);
        lsum0 += rs0;
        lsum1 += rs1;

        // --- O += P V (P fp16 A-frags in-register, single MMA) ---
#pragma unroll
        for (int j2 = 0; j2 < 4; j2++) {
            uint32_t ph[4];
            ph[0] = packh2(s[2 * j2][0],     s[2 * j2][1]);
            ph[1] = packh2(s[2 * j2][2],     s[2 * j2][3]);
            ph[2] = packh2(s[2 * j2 + 1][0], s[2 * j2 + 1][1]);
            ph[3] = packh2(s[2 * j2 + 1][2], s[2 * j2 + 1][3]);
#pragma unroll
            for (int d2 = 0; d2 < 8; d2++) {
                uint32_t vh[4];
                uint32_t vaddr = vb + ((j2 * 16 + vbrow) * AST + d2 * 16 + vbcol) * 2;
                ldmx4t(vh, vaddr);
                mma16816f(o_[2 * d2],     ph[0], ph[1], ph[2], ph[3], vh[0], vh[1]);
                mma16816f(o_[2 * d2 + 1], ph[0], ph[1], ph[2], ph[3], vh[2], vh[3]);
            }
        }
        __syncthreads();
    }

    // --- epilogue ---
    if (!split_kv) {
        const float inv0 = 1.f / lsum0;
        const float inv1 = 1.f / lsum1;
        const size_t gr0 = ((size_t)b * S_LEN + q0 + r0l) * H_DIM;
        const size_t gr1 = gr0 + 8 * H_DIM;
#pragma unroll
        for (int dn = 0; dn < 16; dn++) {
            int col = dn * 8 + colb;
            *(float2*)&out[gr0 + col] = make_float2(o_[dn][0] * inv0, o_[dn][1] * inv0);
            *(float2*)&out[gr1 + col] = make_float2(o_[dn][2] * inv1, o_[dn][3] * inv1);
        }
    } else {
        const size_t pbase = (size_t)(h * 8 + b) * 1024 + (q0 - 1024);
        float* p0 = &g_po[(pbase + r0l) * 128];
        float* p1 = &g_po[(pbase + r1l) * 128];
#pragma unroll
        for (int dn = 0; dn < 16; dn++) {
            int col = dn * 8 + colb;
            *(float2*)&p0[col] = make_float2(o_[dn][0], o_[dn][1]);
            *(float2*)&p1[col] = make_float2(o_[dn][2], o_[dn][3]);
        }
        if ((lane & 3) == 0) {
            g_pl[pbase + r0l] = lsum0;
            g_pl[pbase + r1l] = lsum1;
        }
    }
}

// ---------------------------------------------------------------------------
// Kernel 3: combine split-KV partials (rows 1024..2047 of each batch)
// ---------------------------------------------------------------------------
__global__ __launch_bounds__(256)
void combine_kernel(float* __restrict__ out)
{
    int idx = blockIdx.x * 256 + threadIdx.x;
    int row = idx >> 5;
    int d4  = (idx & 31) * 4;
    int b   = row >> 10;
    int r   = row & 1023;
    float l = g_pl[(size_t)b * 1024 + r] + g_pl[(size_t)(8 + b) * 1024 + r];
    float inv = 1.f / l;
    size_t i0 = ((size_t)b * 1024 + r) * 128 + d4;
    size_t i1 = ((size_t)(8 + b) * 1024 + r) * 128 + d4;
    float4 a = *(const float4*)&g_po[i0];
    float4 c = *(const float4*)&g_po[i1];
    float4 o;
    o.x = (a.x + c.x) * inv;
    o.y = (a.y + c.y) * inv;
    o.z = (a.z + c.z) * inv;
    o.w = (a.w + c.w) * inv;
    *(float4*)&out[((size_t)b * S_LEN + 1024 + r) * H_DIM + d4] = o;
}

// ---------------------------------------------------------------------------
extern "C" void kernel_launch(void* const* d_in, const int* in_sizes, int n_in,
                              void* d_out, int out_size)
{
    const float* X    = (const float*)d_in[0];
    const float* mask = (const float*)d_in[1];
    const float* Wq   = (const float*)d_in[2];
    const float* Wk   = (const float*)d_in[3];
    const float* Wv   = (const float*)d_in[4];
    float* out        = (float*)d_out;

    split_x_kernel<<<M_TOTAL * E_DIM / 4 / 256, 256>>>(X, mask);
    split_w_kernel<<<3 * H_DIM * E_DIM / 4 / 256, 256>>>(Wq, Wk, Wv);

    cudaFuncSetAttribute(qkv_mma_kernel,
                         cudaFuncAttributeMaxDynamicSharedMemorySize, QKV_SMEM);
    dim3 g1(M_TOTAL / 128, 3);
    qkv_mma_kernel<<<g1, 128, QKV_SMEM>>>();

    cudaFuncSetAttribute(attn_mma_kernel,
                         cudaFuncAttributeMaxDynamicSharedMemorySize, ATT_SMEM);
    dim3 g2(24, B_SZ);
    attn_mma_kernel<<<g2, 256, ATT_SMEM>>>(out);

    combine_kernel<<<1024, 256>>>(out);
}